// round 4
// baseline (speedup 1.0000x reference)
#include <cuda_runtime.h>
#include <math.h>

#define SEQ   2048
#define ND    1024
#define NH    16
#define DH    64
#define NPOS  64

// ---------------- scratch (device globals: allocation-free) ----------------
__device__ float g_Q[SEQ * ND];
__device__ float g_K[SEQ * ND];
__device__ float g_V[SEQ * ND];
__device__ float g_ctx[SEQ * ND];
__device__ float g_logits[(size_t)NH * SEQ * SEQ];   // 256 MB
__device__ float g_li[NH * SEQ * NPOS];              // 8 MB

// ---------------- Y[M,N] = X[M,K] @ W[N,K]^T + bias, M=SEQ, N=K=ND ----------
__global__ __launch_bounds__(256) void gemm_bias_kernel(
    const float* __restrict__ X, const float* __restrict__ W,
    const float* __restrict__ bias, float* __restrict__ Y)
{
    __shared__ float Xs[64][17];
    __shared__ float Ws[64][17];
    const int tid = threadIdx.x;
    const int tx = tid & 15, ty = tid >> 4;
    const int m0 = blockIdx.y * 64, n0 = blockIdx.x * 64;

    float acc[4][4] = {};
    for (int kt = 0; kt < ND; kt += 16) {
        #pragma unroll
        for (int i = tid; i < 64 * 16; i += 256) {
            int r = i >> 4, c = i & 15;
            Xs[r][c] = X[(m0 + r) * ND + kt + c];
            Ws[r][c] = W[(n0 + r) * ND + kt + c];
        }
        __syncthreads();
        #pragma unroll
        for (int k = 0; k < 16; k++) {
            float a[4], b[4];
            #pragma unroll
            for (int i = 0; i < 4; i++) a[i] = Xs[ty * 4 + i][k];
            #pragma unroll
            for (int j = 0; j < 4; j++) b[j] = Ws[tx * 4 + j][k];
            #pragma unroll
            for (int i = 0; i < 4; i++)
                #pragma unroll
                for (int j = 0; j < 4; j++) acc[i][j] += a[i] * b[j];
        }
        __syncthreads();
    }
    #pragma unroll
    for (int i = 0; i < 4; i++)
        #pragma unroll
        for (int j = 0; j < 4; j++)
            Y[(m0 + ty * 4 + i) * ND + n0 + tx * 4 + j] = acc[i][j] + bias[n0 + tx * 4 + j];
}

// -------- logits[h,q,k] = 0.125 * dot64(Q[q, h*64+:], K[k, h*64+:]) ---------
__global__ __launch_bounds__(256) void qk_kernel()
{
    __shared__ float Qs[64][65];
    __shared__ float Ks[64][65];
    const int tid = threadIdx.x;
    const int tx = tid & 15, ty = tid >> 4;
    const int h = blockIdx.z;
    const int q0 = blockIdx.y * 64, k0 = blockIdx.x * 64;

    for (int i = tid; i < 64 * 64; i += 256) {
        int r = i >> 6, c = i & 63;
        Qs[r][c] = g_Q[(q0 + r) * ND + h * DH + c];
        Ks[r][c] = g_K[(k0 + r) * ND + h * DH + c];
    }
    __syncthreads();

    float acc[4][4] = {};
    #pragma unroll 8
    for (int k = 0; k < 64; k++) {
        float a[4], b[4];
        #pragma unroll
        for (int i = 0; i < 4; i++) a[i] = Qs[ty * 4 + i][k];
        #pragma unroll
        for (int j = 0; j < 4; j++) b[j] = Ks[tx * 4 + j][k];
        #pragma unroll
        for (int i = 0; i < 4; i++)
            #pragma unroll
            for (int j = 0; j < 4; j++) acc[i][j] += a[i] * b[j];
    }
    float* out = g_logits + ((size_t)h * SEQ + q0) * SEQ + k0;
    #pragma unroll
    for (int i = 0; i < 4; i++)
        #pragma unroll
        for (int j = 0; j < 4; j++)
            out[(size_t)(ty * 4 + i) * SEQ + tx * 4 + j] = acc[i][j] * 0.125f;
}

// -------- li[h,q,n] = sum_d Q[q, h*64+d] * pos_emb[d, n] --------------------
__global__ __launch_bounds__(256) void li_kernel(const float* __restrict__ pos_emb)
{
    __shared__ float Qs[64][65];
    __shared__ float Ps[64][65];
    const int tid = threadIdx.x;
    const int tx = tid & 15, ty = tid >> 4;
    const int h = blockIdx.y;
    const int q0 = blockIdx.x * 64;

    for (int i = tid; i < 64 * 64; i += 256) {
        int r = i >> 6, c = i & 63;
        Qs[r][c] = g_Q[(q0 + r) * ND + h * DH + c];
        Ps[r][c] = pos_emb[r * NPOS + c];
    }
    __syncthreads();

    float acc[4][4] = {};
    #pragma unroll 8
    for (int d = 0; d < 64; d++) {
        float a[4], b[4];
        #pragma unroll
        for (int i = 0; i < 4; i++) a[i] = Qs[ty * 4 + i][d];
        #pragma unroll
        for (int j = 0; j < 4; j++) b[j] = Ps[d][tx * 4 + j];
        #pragma unroll
        for (int i = 0; i < 4; i++)
            #pragma unroll
            for (int j = 0; j < 4; j++) acc[i][j] += a[i] * b[j];
    }
    #pragma unroll
    for (int i = 0; i < 4; i++)
        #pragma unroll
        for (int j = 0; j < 4; j++)
            g_li[(h * SEQ + q0 + ty * 4 + i) * NPOS + tx * 4 + j] = acc[i][j];
}

// -------- per (h,q) row: gates -> suffix-cumsum -> CoPE interp -> softmax ---
__global__ __launch_bounds__(256) void cope_softmax_kernel()
{
    __shared__ float row[SEQ];
    __shared__ float gs[SEQ];
    __shared__ float li[NPOS];
    __shared__ float part[256];
    __shared__ float red[256];

    const int tid = threadIdx.x;
    const int q = blockIdx.x, h = blockIdx.y;
    float* lrow = g_logits + ((size_t)h * SEQ + q) * SEQ;

    for (int k = tid; k < SEQ; k += 256) {
        float x = lrow[k];
        row[k] = x;
        gs[k] = 1.0f / (1.0f + __expf(-x));
    }
    if (tid < NPOS) li[tid] = g_li[(h * SEQ + q) * NPOS + tid];
    __syncthreads();

    // reverse (suffix) inclusive cumsum: per-thread chunk of 8, then scan of sums
    const int base = tid * 8;
    float csum = 0.0f;
    #pragma unroll
    for (int j = 7; j >= 0; --j) { csum += gs[base + j]; gs[base + j] = csum; }
    part[tid] = csum;
    __syncthreads();
    for (int d = 1; d < 256; d <<= 1) {
        float v = (tid + d < 256) ? part[tid + d] : 0.0f;
        __syncthreads();
        part[tid] += v;
        __syncthreads();
    }
    const float off = part[tid] - csum;   // sum over later chunks

    float lmax = -INFINITY;
    #pragma unroll
    for (int j = 0; j < 8; j++) {
        float pos = gs[base + j] + off;
        pos = fminf(pos, (float)(NPOS - 1));
        float pf = floorf(pos);
        int fi = (int)pf;
        int ci = (int)ceilf(pos);
        float w = pos - pf;
        float cope = li[ci] * w + li[fi] * (1.0f - w);
        float tot = row[base + j] + cope;
        row[base + j] = tot;
        lmax = fmaxf(lmax, tot);
    }
    red[tid] = lmax;
    __syncthreads();
    for (int d = 128; d > 0; d >>= 1) {
        if (tid < d) red[tid] = fmaxf(red[tid], red[tid + d]);
        __syncthreads();
    }
    const float mx = red[0];
    __syncthreads();

    float lsum = 0.0f;
    #pragma unroll
    for (int j = 0; j < 8; j++) {
        float e = __expf(row[base + j] - mx);
        row[base + j] = e;
        lsum += e;
    }
    red[tid] = lsum;
    __syncthreads();
    for (int d = 128; d > 0; d >>= 1) {
        if (tid < d) red[tid] += red[tid + d];
        __syncthreads();
    }
    const float inv = 1.0f / red[0];
    #pragma unroll
    for (int j = 0; j < 8; j++) lrow[base + j] = row[base + j] * inv;
}

// -------- ctx[q, h*64+n] = sum_k scores[h,q,k] * V[k, h*64+n] ---------------
__global__ __launch_bounds__(256) void ctx_kernel()
{
    __shared__ float Ps[64][33];
    __shared__ float Vs[32][65];
    const int tid = threadIdx.x;
    const int tx = tid & 15, ty = tid >> 4;
    const int h = blockIdx.y;
    const int q0 = blockIdx.x * 64;
    const float* P = g_logits + (size_t)h * SEQ * SEQ;

    float acc[4][4] = {};
    for (int kt = 0; kt < SEQ; kt += 32) {
        for (int i = tid; i < 64 * 32; i += 256) {
            int r = i >> 5, c = i & 31;
            Ps[r][c] = P[(size_t)(q0 + r) * SEQ + kt + c];
        }
        for (int i = tid; i < 32 * 64; i += 256) {
            int r = i >> 6, c = i & 63;
            Vs[r][c] = g_V[(kt + r) * ND + h * DH + c];
        }
        __syncthreads();
        #pragma unroll
        for (int k = 0; k < 32; k++) {
            float a[4], b[4];
            #pragma unroll
            for (int i = 0; i < 4; i++) a[i] = Ps[ty * 4 + i][k];
            #pragma unroll
            for (int j = 0; j < 4; j++) b[j] = Vs[k][tx * 4 + j];
            #pragma unroll
            for (int i = 0; i < 4; i++)
                #pragma unroll
                for (int j = 0; j < 4; j++) acc[i][j] += a[i] * b[j];
        }
        __syncthreads();
    }
    #pragma unroll
    for (int i = 0; i < 4; i++)
        #pragma unroll
        for (int j = 0; j < 4; j++)
            g_ctx[(q0 + ty * 4 + i) * ND + h * DH + tx * 4 + j] = acc[i][j];
}

// ---------------------------------------------------------------------------
extern "C" void kernel_launch(void* const* d_in, const int* in_sizes, int n_in,
                              void* d_out, int out_size)
{
    const float* q      = (const float*)d_in[0];
    const float* k      = (const float*)d_in[1];
    const float* v      = (const float*)d_in[2];
    const float* Wq_w   = (const float*)d_in[3];
    const float* Wq_b   = (const float*)d_in[4];
    const float* Wk_w   = (const float*)d_in[5];
    const float* Wk_b   = (const float*)d_in[6];
    const float* Wv_w   = (const float*)d_in[7];
    const float* Wv_b   = (const float*)d_in[8];
    const float* Wo_w   = (const float*)d_in[9];
    const float* Wo_b   = (const float*)d_in[10];
    const float* pos_emb= (const float*)d_in[11];
    float* out = (float*)d_out;

    float *Qp, *Kp, *Vp, *Cp;
    cudaGetSymbolAddress((void**)&Qp, g_Q);
    cudaGetSymbolAddress((void**)&Kp, g_K);
    cudaGetSymbolAddress((void**)&Vp, g_V);
    cudaGetSymbolAddress((void**)&Cp, g_ctx);

    dim3 gProj(ND / 64, SEQ / 64);          // (16, 32)
    gemm_bias_kernel<<<gProj, 256>>>(q, Wq_w, Wq_b, Qp);
    gemm_bias_kernel<<<gProj, 256>>>(k, Wk_w, Wk_b, Kp);
    gemm_bias_kernel<<<gProj, 256>>>(v, Wv_w, Wv_b, Vp);

    qk_kernel<<<dim3(SEQ / 64, SEQ / 64, NH), 256>>>();
    li_kernel<<<dim3(SEQ / 64, NH), 256>>>(pos_emb);
    cope_softmax_kernel<<<dim3(SEQ, NH), 256>>>();
    ctx_kernel<<<dim3(SEQ / 64, NH), 256>>>();

    gemm_bias_kernel<<<gProj, 256>>>(Cp, Wo_w, Wo_b, out);
}

// round 5
// speedup vs baseline: 1.9356x; 1.9356x over previous
#include <cuda_runtime.h>
#include <math.h>

#define SEQ   2048
#define ND    1024
#define NH    16
#define DH    64
#define NPOS  64

// ---------------- scratch (device globals: allocation-free) ----------------
__device__ float g_Q[SEQ * ND];
__device__ float g_K[SEQ * ND];
__device__ float g_V[SEQ * ND];
__device__ float g_ctx[SEQ * ND];
__device__ float g_logits[(size_t)NH * SEQ * SEQ];   // 256 MB
__device__ float g_li[NH * SEQ * NPOS];              // 8 MB

// ---------------- Y[M,N] = X[M,K] @ W[N,K]^T + bias, M=SEQ, N=K=ND ----------
// 128x128 tile, BK=16, 256 threads, 8x8 per thread, transposed smem.
__global__ __launch_bounds__(256, 2) void gemm_bias_kernel(
    const float* __restrict__ X, const float* __restrict__ W,
    const float* __restrict__ bias, float* __restrict__ Y)
{
    __shared__ float Xs[16][132];
    __shared__ float Ws[16][132];
    const int tid = threadIdx.x;
    const int tx = tid & 15, ty = tid >> 4;
    const int m0 = blockIdx.y * 128, n0 = blockIdx.x * 128;

    const int lc = (tid & 3) * 4;   // k within 16
    const int lr = tid >> 2;        // 0..63, +64 second pass

    float acc[8][8] = {};
    for (int kt = 0; kt < ND; kt += 16) {
        #pragma unroll
        for (int it = 0; it < 2; it++) {
            int r = lr + it * 64;
            float4 xv = *(const float4*)&X[(size_t)(m0 + r) * ND + kt + lc];
            float4 wv = *(const float4*)&W[(size_t)(n0 + r) * ND + kt + lc];
            Xs[lc + 0][r] = xv.x; Xs[lc + 1][r] = xv.y;
            Xs[lc + 2][r] = xv.z; Xs[lc + 3][r] = xv.w;
            Ws[lc + 0][r] = wv.x; Ws[lc + 1][r] = wv.y;
            Ws[lc + 2][r] = wv.z; Ws[lc + 3][r] = wv.w;
        }
        __syncthreads();
        #pragma unroll
        for (int k = 0; k < 16; k++) {
            float a[8], b[8];
            *(float4*)&a[0] = *(const float4*)&Xs[k][ty * 8];
            *(float4*)&a[4] = *(const float4*)&Xs[k][ty * 8 + 4];
            *(float4*)&b[0] = *(const float4*)&Ws[k][tx * 8];
            *(float4*)&b[4] = *(const float4*)&Ws[k][tx * 8 + 4];
            #pragma unroll
            for (int i = 0; i < 8; i++)
                #pragma unroll
                for (int j = 0; j < 8; j++) acc[i][j] += a[i] * b[j];
        }
        __syncthreads();
    }
    float bv[8];
    #pragma unroll
    for (int j = 0; j < 8; j++) bv[j] = bias[n0 + tx * 8 + j];
    #pragma unroll
    for (int i = 0; i < 8; i++) {
        float* yrow = &Y[(size_t)(m0 + ty * 8 + i) * ND + n0 + tx * 8];
        float4 o0, o1;
        o0.x = acc[i][0] + bv[0]; o0.y = acc[i][1] + bv[1];
        o0.z = acc[i][2] + bv[2]; o0.w = acc[i][3] + bv[3];
        o1.x = acc[i][4] + bv[4]; o1.y = acc[i][5] + bv[5];
        o1.z = acc[i][6] + bv[6]; o1.w = acc[i][7] + bv[7];
        *(float4*)&yrow[0] = o0;
        *(float4*)&yrow[4] = o1;
    }
}

// -------- logits[h,q,k] = 0.125 * dot64(Q[q,h*64+:], K[k,h*64+:]) -----------
// 128x128 tile, BK=32 (2 passes over DH=64), 8x8 per thread.
__global__ __launch_bounds__(256, 2) void qk_kernel()
{
    __shared__ float Qs[32][132];
    __shared__ float Ks[32][132];
    const int tid = threadIdx.x;
    const int tx = tid & 15, ty = tid >> 4;
    const int h = blockIdx.z;
    const int q0 = blockIdx.y * 128, k0 = blockIdx.x * 128;

    const int lc = (tid & 7) * 4;   // k within 32
    const int lr = tid >> 3;        // 0..31, 4 passes

    float acc[8][8] = {};
    #pragma unroll
    for (int kt = 0; kt < DH; kt += 32) {
        #pragma unroll
        for (int it = 0; it < 4; it++) {
            int r = lr + it * 32;
            float4 qv = *(const float4*)&g_Q[(size_t)(q0 + r) * ND + h * DH + kt + lc];
            float4 kv = *(const float4*)&g_K[(size_t)(k0 + r) * ND + h * DH + kt + lc];
            Qs[lc + 0][r] = qv.x; Qs[lc + 1][r] = qv.y;
            Qs[lc + 2][r] = qv.z; Qs[lc + 3][r] = qv.w;
            Ks[lc + 0][r] = kv.x; Ks[lc + 1][r] = kv.y;
            Ks[lc + 2][r] = kv.z; Ks[lc + 3][r] = kv.w;
        }
        __syncthreads();
        #pragma unroll
        for (int k = 0; k < 32; k++) {
            float a[8], b[8];
            *(float4*)&a[0] = *(const float4*)&Qs[k][ty * 8];
            *(float4*)&a[4] = *(const float4*)&Qs[k][ty * 8 + 4];
            *(float4*)&b[0] = *(const float4*)&Ks[k][tx * 8];
            *(float4*)&b[4] = *(const float4*)&Ks[k][tx * 8 + 4];
            #pragma unroll
            for (int i = 0; i < 8; i++)
                #pragma unroll
                for (int j = 0; j < 8; j++) acc[i][j] += a[i] * b[j];
        }
        __syncthreads();
    }
    float* out = g_logits + ((size_t)h * SEQ + q0) * SEQ + k0;
    #pragma unroll
    for (int i = 0; i < 8; i++) {
        float* orow = &out[(size_t)(ty * 8 + i) * SEQ + tx * 8];
        float4 o0, o1;
        o0.x = acc[i][0] * 0.125f; o0.y = acc[i][1] * 0.125f;
        o0.z = acc[i][2] * 0.125f; o0.w = acc[i][3] * 0.125f;
        o1.x = acc[i][4] * 0.125f; o1.y = acc[i][5] * 0.125f;
        o1.z = acc[i][6] * 0.125f; o1.w = acc[i][7] * 0.125f;
        *(float4*)&orow[0] = o0;
        *(float4*)&orow[4] = o1;
    }
}

// -------- li[h,q,n] = sum_d Q[q, h*64+d] * pos_emb[d, n] --------------------
__global__ __launch_bounds__(256) void li_kernel(const float* __restrict__ pos_emb)
{
    __shared__ float Qs[64][65];
    __shared__ float Ps[64][65];
    const int tid = threadIdx.x;
    const int tx = tid & 15, ty = tid >> 4;
    const int h = blockIdx.y;
    const int q0 = blockIdx.x * 64;

    for (int i = tid; i < 64 * 64; i += 256) {
        int r = i >> 6, c = i & 63;
        Qs[r][c] = g_Q[(q0 + r) * ND + h * DH + c];
        Ps[r][c] = pos_emb[r * NPOS + c];
    }
    __syncthreads();

    float acc[4][4] = {};
    #pragma unroll 8
    for (int d = 0; d < 64; d++) {
        float a[4], b[4];
        #pragma unroll
        for (int i = 0; i < 4; i++) a[i] = Qs[ty * 4 + i][d];
        #pragma unroll
        for (int j = 0; j < 4; j++) b[j] = Ps[d][tx * 4 + j];
        #pragma unroll
        for (int i = 0; i < 4; i++)
            #pragma unroll
            for (int j = 0; j < 4; j++) acc[i][j] += a[i] * b[j];
    }
    #pragma unroll
    for (int i = 0; i < 4; i++)
        #pragma unroll
        for (int j = 0; j < 4; j++)
            g_li[(h * SEQ + q0 + ty * 4 + i) * NPOS + tx * 4 + j] = acc[i][j];
}

// -------- per (h,q) row: gates -> suffix-cumsum -> CoPE interp -> softmax ---
// Row lives in registers (8/thread). Warp-shuffle scan. sigmoid via tanh.approx.
__global__ __launch_bounds__(256) void cope_softmax_kernel()
{
    __shared__ float li[NPOS];
    __shared__ float wsum[8];
    __shared__ float redm[8];
    __shared__ float reds[8];

    const int tid = threadIdx.x;
    const int lane = tid & 31, warp = tid >> 5;
    const int q = blockIdx.x, h = blockIdx.y;
    float* lrow = g_logits + ((size_t)h * SEQ + q) * SEQ;

    if (tid < NPOS) li[tid] = g_li[(h * SEQ + q) * NPOS + tid];

    const int base = tid * 8;
    float x[8];
    *(float4*)&x[0] = *(const float4*)&lrow[base];
    *(float4*)&x[4] = *(const float4*)&lrow[base + 4];

    // gates + per-thread suffix cumsum (descending within chunk)
    float g[8];
    float csum = 0.0f;
    #pragma unroll
    for (int j = 7; j >= 0; --j) {
        float t;
        asm("tanh.approx.f32 %0, %1;" : "=f"(t) : "f"(x[j] * 0.5f));
        csum += fmaf(t, 0.5f, 0.5f);     // sigmoid(x) = 0.5*tanh(x/2)+0.5
        g[j] = csum;
    }
    // inclusive prefix of chunk sums (ascending tid), warp-shuffle
    float v = csum;
    #pragma unroll
    for (int d = 1; d < 32; d <<= 1) {
        float n = __shfl_up_sync(0xffffffffu, v, d);
        if (lane >= d) v += n;
    }
    if (lane == 31) wsum[warp] = v;
    __syncthreads();
    float wpre = 0.0f, total = 0.0f;
    #pragma unroll
    for (int w = 0; w < 8; w++) {
        float s = wsum[w];
        if (w < warp) wpre += s;
        total += s;
    }
    const float off = total - (wpre + v);   // sum over strictly later threads

    // CoPE interpolation + running max
    float lmax = -INFINITY;
    #pragma unroll
    for (int j = 0; j < 8; j++) {
        float pos = fminf(g[j] + off, (float)(NPOS - 1));
        float pf = floorf(pos);
        int fi = (int)pf;
        int ci = (int)ceilf(pos);
        float w = pos - pf;
        x[j] += li[ci] * w + li[fi] * (1.0f - w);
        lmax = fmaxf(lmax, x[j]);
    }
    #pragma unroll
    for (int d = 16; d > 0; d >>= 1)
        lmax = fmaxf(lmax, __shfl_xor_sync(0xffffffffu, lmax, d));
    if (lane == 0) redm[warp] = lmax;
    __syncthreads();
    float mx = redm[0];
    #pragma unroll
    for (int w = 1; w < 8; w++) mx = fmaxf(mx, redm[w]);

    float lsum = 0.0f;
    #pragma unroll
    for (int j = 0; j < 8; j++) {
        x[j] = __expf(x[j] - mx);
        lsum += x[j];
    }
    #pragma unroll
    for (int d = 16; d > 0; d >>= 1)
        lsum += __shfl_xor_sync(0xffffffffu, lsum, d);
    if (lane == 0) reds[warp] = lsum;
    __syncthreads();
    float tsum = 0.0f;
    #pragma unroll
    for (int w = 0; w < 8; w++) tsum += reds[w];
    const float inv = 1.0f / tsum;

    float4 o0, o1;
    o0.x = x[0] * inv; o0.y = x[1] * inv; o0.z = x[2] * inv; o0.w = x[3] * inv;
    o1.x = x[4] * inv; o1.y = x[5] * inv; o1.z = x[6] * inv; o1.w = x[7] * inv;
    *(float4*)&lrow[base]     = o0;
    *(float4*)&lrow[base + 4] = o1;
}

// -------- ctx[q, h*64+n] = sum_k scores[h,q,k] * V[k, h*64+n] ---------------
// 128(q) x 64(n) tile, BK=32, 256 threads, 8x4 per thread.
__global__ __launch_bounds__(256, 2) void ctx_kernel()
{
    __shared__ float Ps[32][132];   // [k][q] transposed
    __shared__ float Vs[32][68];    // [k][n]
    const int tid = threadIdx.x;
    const int tx = tid & 15, ty = tid >> 4;
    const int h = blockIdx.y;
    const int q0 = blockIdx.x * 128;
    const float* P = g_logits + (size_t)h * SEQ * SEQ;

    const int plc = (tid & 7) * 4;  // k within 32
    const int plr = tid >> 3;       // 0..31, 4 passes of q-rows
    const int vlc = (tid & 15) * 4; // n within 64
    const int vlr = tid >> 4;       // 0..15, 2 passes of k-rows

    float acc[8][4] = {};
    for (int kt = 0; kt < SEQ; kt += 32) {
        #pragma unroll
        for (int it = 0; it < 4; it++) {
            int r = plr + it * 32;
            float4 pv = *(const float4*)&P[(size_t)(q0 + r) * SEQ + kt + plc];
            Ps[plc + 0][r] = pv.x; Ps[plc + 1][r] = pv.y;
            Ps[plc + 2][r] = pv.z; Ps[plc + 3][r] = pv.w;
        }
        #pragma unroll
        for (int it = 0; it < 2; it++) {
            int r = vlr + it * 16;
            *(float4*)&Vs[r][vlc] =
                *(const float4*)&g_V[(size_t)(kt + r) * ND + h * DH + vlc];
        }
        __syncthreads();
        #pragma unroll
        for (int k = 0; k < 32; k++) {
            float a[8], b[4];
            *(float4*)&a[0] = *(const float4*)&Ps[k][ty * 8];
            *(float4*)&a[4] = *(const float4*)&Ps[k][ty * 8 + 4];
            *(float4*)&b[0] = *(const float4*)&Vs[k][tx * 4];
            #pragma unroll
            for (int i = 0; i < 8; i++)
                #pragma unroll
                for (int j = 0; j < 4; j++) acc[i][j] += a[i] * b[j];
        }
        __syncthreads();
    }
    #pragma unroll
    for (int i = 0; i < 8; i++) {
        float4 o;
        o.x = acc[i][0]; o.y = acc[i][1]; o.z = acc[i][2]; o.w = acc[i][3];
        *(float4*)&g_ctx[(size_t)(q0 + ty * 8 + i) * ND + h * DH + tx * 4] = o;
    }
}

// ---------------------------------------------------------------------------
extern "C" void kernel_launch(void* const* d_in, const int* in_sizes, int n_in,
                              void* d_out, int out_size)
{
    const float* q      = (const float*)d_in[0];
    const float* k      = (const float*)d_in[1];
    const float* v      = (const float*)d_in[2];
    const float* Wq_w   = (const float*)d_in[3];
    const float* Wq_b   = (const float*)d_in[4];
    const float* Wk_w   = (const float*)d_in[5];
    const float* Wk_b   = (const float*)d_in[6];
    const float* Wv_w   = (const float*)d_in[7];
    const float* Wv_b   = (const float*)d_in[8];
    const float* Wo_w   = (const float*)d_in[9];
    const float* Wo_b   = (const float*)d_in[10];
    const float* pos_emb= (const float*)d_in[11];
    float* out = (float*)d_out;

    float *Qp, *Kp, *Vp, *Cp;
    cudaGetSymbolAddress((void**)&Qp, g_Q);
    cudaGetSymbolAddress((void**)&Kp, g_K);
    cudaGetSymbolAddress((void**)&Vp, g_V);
    cudaGetSymbolAddress((void**)&Cp, g_ctx);

    dim3 gProj(ND / 128, SEQ / 128);        // (8, 16)
    gemm_bias_kernel<<<gProj, 256>>>(q, Wq_w, Wq_b, Qp);
    gemm_bias_kernel<<<gProj, 256>>>(k, Wk_w, Wk_b, Kp);
    gemm_bias_kernel<<<gProj, 256>>>(v, Wv_w, Wv_b, Vp);

    qk_kernel<<<dim3(SEQ / 128, SEQ / 128, NH), 256>>>();
    li_kernel<<<dim3(SEQ / 64, NH), 256>>>(pos_emb);
    cope_softmax_kernel<<<dim3(SEQ, NH), 256>>>();
    ctx_kernel<<<dim3(SEQ / 128, NH), 256>>>();

    gemm_bias_kernel<<<gProj, 256>>>(Cp, Wo_w, Wo_b, out);
}

// round 6
// speedup vs baseline: 3.2075x; 1.6571x over previous
#include <cuda_runtime.h>
#include <cuda_bf16.h>
#include <math.h>
#include <stdint.h>

#define SEQ   2048
#define ND    1024
#define NH    16
#define DH    64
#define NPOS  64

typedef __nv_bfloat16 bf16;
typedef __nv_bfloat162 bf162;

// ---------------- scratch (device globals: allocation-free) ----------------
__device__ float g_Q[SEQ * ND];                       // fp32 Q (li_kernel)
__device__ float g_logits[(size_t)NH * SEQ * SEQ];    // 256 MB fp32 logits
__device__ float g_li[NH * SEQ * NPOS];

__device__ bf16 g_inqh[SEQ * ND], g_inql[SEQ * ND];
__device__ bf16 g_inkh[SEQ * ND], g_inkl[SEQ * ND];
__device__ bf16 g_invh[SEQ * ND], g_invl[SEQ * ND];
__device__ bf16 g_wqh[ND * ND], g_wql[ND * ND];
__device__ bf16 g_wkh[ND * ND], g_wkl[ND * ND];
__device__ bf16 g_wvh[ND * ND], g_wvl[ND * ND];
__device__ bf16 g_woh[ND * ND], g_wol[ND * ND];
__device__ bf16 g_Qh[SEQ * ND], g_Ql[SEQ * ND];
__device__ bf16 g_Kh[SEQ * ND], g_Kl[SEQ * ND];
__device__ bf16 g_Vh[SEQ * ND], g_Vl[SEQ * ND];
__device__ bf16 g_ctxh[SEQ * ND], g_ctxl[SEQ * ND];
__device__ bf16 g_Sh[(size_t)NH * SEQ * SEQ];         // scores hi
__device__ bf16 g_Sl[(size_t)NH * SEQ * SEQ];         // scores lo

// ---------------- PTX helpers ----------------------------------------------
__device__ __forceinline__ uint32_t smem_u32(const void* p) {
    return (uint32_t)__cvta_generic_to_shared(p);
}
__device__ __forceinline__ void ldsm4(uint32_t* r, uint32_t a) {
    asm volatile("ldmatrix.sync.aligned.m8n8.x4.shared.b16 {%0,%1,%2,%3}, [%4];"
                 : "=r"(r[0]), "=r"(r[1]), "=r"(r[2]), "=r"(r[3]) : "r"(a));
}
__device__ __forceinline__ void ldsm4t(uint32_t* r, uint32_t a) {
    asm volatile("ldmatrix.sync.aligned.m8n8.x4.trans.shared.b16 {%0,%1,%2,%3}, [%4];"
                 : "=r"(r[0]), "=r"(r[1]), "=r"(r[2]), "=r"(r[3]) : "r"(a));
}
__device__ __forceinline__ void mma16816(float* c, const uint32_t* a, const uint32_t* b) {
    asm volatile(
        "mma.sync.aligned.m16n8k16.row.col.f32.bf16.bf16.f32 "
        "{%0,%1,%2,%3}, {%4,%5,%6,%7}, {%8,%9}, {%0,%1,%2,%3};"
        : "+f"(c[0]), "+f"(c[1]), "+f"(c[2]), "+f"(c[3])
        : "r"(a[0]), "r"(a[1]), "r"(a[2]), "r"(a[3]), "r"(b[0]), "r"(b[1]));
}

// ---------------- split fp32 -> bf16 hi + bf16 lo ---------------------------
__global__ __launch_bounds__(256) void split_kernel(
    const float* __restrict__ s, bf16* __restrict__ hi, bf16* __restrict__ lo)
{
    int i = (blockIdx.x * 256 + threadIdx.x) * 4;
    float4 v = *(const float4*)&s[i];
    bf16 h0 = __float2bfloat16_rn(v.x), h1 = __float2bfloat16_rn(v.y);
    bf16 h2 = __float2bfloat16_rn(v.z), h3 = __float2bfloat16_rn(v.w);
    bf16 l0 = __float2bfloat16_rn(v.x - __bfloat162float(h0));
    bf16 l1 = __float2bfloat16_rn(v.y - __bfloat162float(h1));
    bf16 l2 = __float2bfloat16_rn(v.z - __bfloat162float(h2));
    bf16 l3 = __float2bfloat16_rn(v.w - __bfloat162float(h3));
    *(bf162*)&hi[i]     = bf162{h0, h1};
    *(bf162*)&hi[i + 2] = bf162{h2, h3};
    *(bf162*)&lo[i]     = bf162{l0, l1};
    *(bf162*)&lo[i + 2] = bf162{l2, l3};
}

// ---------------- Y = X @ W^T + bias (split-bf16 MMA) -----------------------
// Block 128x64, BK=32, 8 warps (warp tile 32x32, 4m x 2n).
#define KST 40   // 32 + 8 pad

__global__ __launch_bounds__(256, 2) void mm_bias_kernel(
    const bf16* __restrict__ Xh, const bf16* __restrict__ Xl,
    const bf16* __restrict__ Wh, const bf16* __restrict__ Wl,
    const float* __restrict__ bias,
    float* __restrict__ Yf, bf16* __restrict__ Yh, bf16* __restrict__ Yl)
{
    __shared__ bf16 Xsh[128][KST], Xsl[128][KST];
    __shared__ bf16 Wsh[64][KST],  Wsl[64][KST];
    const int tid = threadIdx.x, lane = tid & 31, warp = tid >> 5;
    const int wm = warp & 3, wn = warp >> 2;
    const int m0 = blockIdx.y * 128, n0 = blockIdx.x * 64;

    const int xr = tid >> 2, xc = (tid & 3) * 8;

    float acc[2][4][4] = {};
    for (int kt = 0; kt < ND; kt += 32) {
        *(uint4*)&Xsh[xr][xc]      = *(const uint4*)&Xh[(size_t)(m0 + xr) * ND + kt + xc];
        *(uint4*)&Xsh[xr + 64][xc] = *(const uint4*)&Xh[(size_t)(m0 + xr + 64) * ND + kt + xc];
        *(uint4*)&Xsl[xr][xc]      = *(const uint4*)&Xl[(size_t)(m0 + xr) * ND + kt + xc];
        *(uint4*)&Xsl[xr + 64][xc] = *(const uint4*)&Xl[(size_t)(m0 + xr + 64) * ND + kt + xc];
        *(uint4*)&Wsh[xr][xc]      = *(const uint4*)&Wh[(size_t)(n0 + xr) * ND + kt + xc];
        *(uint4*)&Wsl[xr][xc]      = *(const uint4*)&Wl[(size_t)(n0 + xr) * ND + kt + xc];
        __syncthreads();
        #pragma unroll
        for (int kk = 0; kk < 32; kk += 16) {
            uint32_t Ah[2][4], Al[2][4], Bh[4][2], Bl[4][2];
            int arow = wm * 32 + (lane & 7) + ((lane >> 3) & 1) * 8;
            int acol = kk + (lane >> 4) * 8;
            ldsm4(Ah[0], smem_u32(&Xsh[arow][acol]));
            ldsm4(Ah[1], smem_u32(&Xsh[arow + 16][acol]));
            ldsm4(Al[0], smem_u32(&Xsl[arow][acol]));
            ldsm4(Al[1], smem_u32(&Xsl[arow + 16][acol]));
            int brow = wn * 32 + (lane >> 4) * 8 + (lane & 7);
            int bcol = kk + ((lane >> 3) & 1) * 8;
            ldsm4(&Bh[0][0], smem_u32(&Wsh[brow][bcol]));
            ldsm4(&Bh[2][0], smem_u32(&Wsh[brow + 16][bcol]));
            ldsm4(&Bl[0][0], smem_u32(&Wsl[brow][bcol]));
            ldsm4(&Bl[2][0], smem_u32(&Wsl[brow + 16][bcol]));
            #pragma unroll
            for (int mt = 0; mt < 2; mt++)
                #pragma unroll
                for (int nt = 0; nt < 4; nt++) {
                    mma16816(acc[mt][nt], Ah[mt], Bh[nt]);
                    mma16816(acc[mt][nt], Ah[mt], Bl[nt]);
                    mma16816(acc[mt][nt], Al[mt], Bh[nt]);
                }
        }
        __syncthreads();
    }
    const int r0 = lane >> 2, cc = (lane & 3) * 2;
    #pragma unroll
    for (int mt = 0; mt < 2; mt++)
        #pragma unroll
        for (int nt = 0; nt < 4; nt++) {
            int m = m0 + wm * 32 + mt * 16 + r0;
            int n = n0 + wn * 32 + nt * 8 + cc;
            float b0 = bias[n], b1 = bias[n + 1];
            float v0 = acc[mt][nt][0] + b0, v1 = acc[mt][nt][1] + b1;
            float v2 = acc[mt][nt][2] + b0, v3 = acc[mt][nt][3] + b1;
            if (Yf) {
                *(float2*)&Yf[(size_t)m * ND + n]       = float2{v0, v1};
                *(float2*)&Yf[(size_t)(m + 8) * ND + n] = float2{v2, v3};
            }
            if (Yh) {
                bf16 h0 = __float2bfloat16_rn(v0), h1 = __float2bfloat16_rn(v1);
                bf16 h2 = __float2bfloat16_rn(v2), h3 = __float2bfloat16_rn(v3);
                *(bf162*)&Yh[(size_t)m * ND + n]       = bf162{h0, h1};
                *(bf162*)&Yh[(size_t)(m + 8) * ND + n] = bf162{h2, h3};
                *(bf162*)&Yl[(size_t)m * ND + n] =
                    bf162{__float2bfloat16_rn(v0 - __bfloat162float(h0)),
                          __float2bfloat16_rn(v1 - __bfloat162float(h1))};
                *(bf162*)&Yl[(size_t)(m + 8) * ND + n] =
                    bf162{__float2bfloat16_rn(v2 - __bfloat162float(h2)),
                          __float2bfloat16_rn(v3 - __bfloat162float(h3))};
            }
        }
}

// ---------------- logits = 0.125 * Q K^T (per head, split-bf16 MMA) ---------
// Block 128(q) x 64(keys), K = DH = 64 (2 BK=32 iters).
__global__ __launch_bounds__(256, 2) void qk_kernel()
{
    __shared__ bf16 Qsh[128][KST], Qsl[128][KST];
    __shared__ bf16 Ksh[64][KST],  Ksl[64][KST];
    const int tid = threadIdx.x, lane = tid & 31, warp = tid >> 5;
    const int wm = warp & 3, wn = warp >> 2;
    const int h = blockIdx.z;
    const int q0 = blockIdx.y * 128, k0 = blockIdx.x * 64;
    const int ho = h * DH;

    const int xr = tid >> 2, xc = (tid & 3) * 8;

    float acc[2][4][4] = {};
    #pragma unroll
    for (int kt = 0; kt < DH; kt += 32) {
        *(uint4*)&Qsh[xr][xc]      = *(const uint4*)&g_Qh[(size_t)(q0 + xr) * ND + ho + kt + xc];
        *(uint4*)&Qsh[xr + 64][xc] = *(const uint4*)&g_Qh[(size_t)(q0 + xr + 64) * ND + ho + kt + xc];
        *(uint4*)&Qsl[xr][xc]      = *(const uint4*)&g_Ql[(size_t)(q0 + xr) * ND + ho + kt + xc];
        *(uint4*)&Qsl[xr + 64][xc] = *(const uint4*)&g_Ql[(size_t)(q0 + xr + 64) * ND + ho + kt + xc];
        *(uint4*)&Ksh[xr][xc]      = *(const uint4*)&g_Kh[(size_t)(k0 + xr) * ND + ho + kt + xc];
        *(uint4*)&Ksl[xr][xc]      = *(const uint4*)&g_Kl[(size_t)(k0 + xr) * ND + ho + kt + xc];
        __syncthreads();
        #pragma unroll
        for (int kk = 0; kk < 32; kk += 16) {
            uint32_t Ah[2][4], Al[2][4], Bh[4][2], Bl[4][2];
            int arow = wm * 32 + (lane & 7) + ((lane >> 3) & 1) * 8;
            int acol = kk + (lane >> 4) * 8;
            ldsm4(Ah[0], smem_u32(&Qsh[arow][acol]));
            ldsm4(Ah[1], smem_u32(&Qsh[arow + 16][acol]));
            ldsm4(Al[0], smem_u32(&Qsl[arow][acol]));
            ldsm4(Al[1], smem_u32(&Qsl[arow + 16][acol]));
            int brow = wn * 32 + (lane >> 4) * 8 + (lane & 7);
            int bcol = kk + ((lane >> 3) & 1) * 8;
            ldsm4(&Bh[0][0], smem_u32(&Ksh[brow][bcol]));
            ldsm4(&Bh[2][0], smem_u32(&Ksh[brow + 16][bcol]));
            ldsm4(&Bl[0][0], smem_u32(&Ksl[brow][bcol]));
            ldsm4(&Bl[2][0], smem_u32(&Ksl[brow + 16][bcol]));
            #pragma unroll
            for (int mt = 0; mt < 2; mt++)
                #pragma unroll
                for (int nt = 0; nt < 4; nt++) {
                    mma16816(acc[mt][nt], Ah[mt], Bh[nt]);
                    mma16816(acc[mt][nt], Ah[mt], Bl[nt]);
                    mma16816(acc[mt][nt], Al[mt], Bh[nt]);
                }
        }
        __syncthreads();
    }
    float* out = g_logits + (size_t)h * SEQ * SEQ;
    const int r0 = lane >> 2, cc = (lane & 3) * 2;
    #pragma unroll
    for (int mt = 0; mt < 2; mt++)
        #pragma unroll
        for (int nt = 0; nt < 4; nt++) {
            int m = q0 + wm * 32 + mt * 16 + r0;
            int n = k0 + wn * 32 + nt * 8 + cc;
            *(float2*)&out[(size_t)m * SEQ + n] =
                float2{acc[mt][nt][0] * 0.125f, acc[mt][nt][1] * 0.125f};
            *(float2*)&out[(size_t)(m + 8) * SEQ + n] =
                float2{acc[mt][nt][2] * 0.125f, acc[mt][nt][3] * 0.125f};
        }
}

// -------- li[h,q,n] = sum_d Q[q, h*64+d] * pos_emb[d, n] --------------------
__global__ __launch_bounds__(256) void li_kernel(const float* __restrict__ pos_emb)
{
    __shared__ float Qs[64][65];
    __shared__ float Ps[64][65];
    const int tid = threadIdx.x;
    const int tx = tid & 15, ty = tid >> 4;
    const int h = blockIdx.y;
    const int q0 = blockIdx.x * 64;

    for (int i = tid; i < 64 * 64; i += 256) {
        int r = i >> 6, c = i & 63;
        Qs[r][c] = g_Q[(q0 + r) * ND + h * DH + c];
        Ps[r][c] = pos_emb[r * NPOS + c];
    }
    __syncthreads();

    float acc[4][4] = {};
    #pragma unroll 8
    for (int d = 0; d < 64; d++) {
        float a[4], b[4];
        #pragma unroll
        for (int i = 0; i < 4; i++) a[i] = Qs[ty * 4 + i][d];
        #pragma unroll
        for (int j = 0; j < 4; j++) b[j] = Ps[d][tx * 4 + j];
        #pragma unroll
        for (int i = 0; i < 4; i++)
            #pragma unroll
            for (int j = 0; j < 4; j++) acc[i][j] += a[i] * b[j];
    }
    #pragma unroll
    for (int i = 0; i < 4; i++)
        #pragma unroll
        for (int j = 0; j < 4; j++)
            g_li[(h * SEQ + q0 + ty * 4 + i) * NPOS + tx * 4 + j] = acc[i][j];
}

// -------- per (h,q) row: gates -> suffix-cumsum -> CoPE -> softmax ----------
// Writes scores as bf16 hi/lo for the ctx MMA.
__global__ __launch_bounds__(256) void cope_softmax_kernel()
{
    __shared__ float li[NPOS];
    __shared__ float wsum[8];
    __shared__ float redm[8];
    __shared__ float reds[8];

    const int tid = threadIdx.x;
    const int lane = tid & 31, warp = tid >> 5;
    const int q = blockIdx.x, h = blockIdx.y;
    const size_t rbase = ((size_t)h * SEQ + q) * SEQ;
    const float* lrow = g_logits + rbase;

    if (tid < NPOS) li[tid] = g_li[(h * SEQ + q) * NPOS + tid];

    const int base = tid * 8;
    float x[8];
    *(float4*)&x[0] = *(const float4*)&lrow[base];
    *(float4*)&x[4] = *(const float4*)&lrow[base + 4];

    float g[8];
    float csum = 0.0f;
    #pragma unroll
    for (int j = 7; j >= 0; --j) {
        float t;
        asm("tanh.approx.f32 %0, %1;" : "=f"(t) : "f"(x[j] * 0.5f));
        csum += fmaf(t, 0.5f, 0.5f);
        g[j] = csum;
    }
    float v = csum;
    #pragma unroll
    for (int d = 1; d < 32; d <<= 1) {
        float n = __shfl_up_sync(0xffffffffu, v, d);
        if (lane >= d) v += n;
    }
    if (lane == 31) wsum[warp] = v;
    __syncthreads();
    float wpre = 0.0f, total = 0.0f;
    #pragma unroll
    for (int w = 0; w < 8; w++) {
        float s = wsum[w];
        if (w < warp) wpre += s;
        total += s;
    }
    const float off = total - (wpre + v);

    float lmax = -INFINITY;
    #pragma unroll
    for (int j = 0; j < 8; j++) {
        float pos = fminf(g[j] + off, (float)(NPOS - 1));
        float pf = floorf(pos);
        int fi = (int)pf;
        int ci = (int)ceilf(pos);
        float w = pos - pf;
        x[j] += li[ci] * w + li[fi] * (1.0f - w);
        lmax = fmaxf(lmax, x[j]);
    }
    #pragma unroll
    for (int d = 16; d > 0; d >>= 1)
        lmax = fmaxf(lmax, __shfl_xor_sync(0xffffffffu, lmax, d));
    if (lane == 0) redm[warp] = lmax;
    __syncthreads();
    float mx = redm[0];
    #pragma unroll
    for (int w = 1; w < 8; w++) mx = fmaxf(mx, redm[w]);

    float lsum = 0.0f;
    #pragma unroll
    for (int j = 0; j < 8; j++) {
        x[j] = __expf(x[j] - mx);
        lsum += x[j];
    }
    #pragma unroll
    for (int d = 16; d > 0; d >>= 1)
        lsum += __shfl_xor_sync(0xffffffffu, lsum, d);
    if (lane == 0) reds[warp] = lsum;
    __syncthreads();
    float tsum = 0.0f;
    #pragma unroll
    for (int w = 0; w < 8; w++) tsum += reds[w];
    const float inv = 1.0f / tsum;

    bf16* sh = g_Sh + rbase + base;
    bf16* sl = g_Sl + rbase + base;
    #pragma unroll
    for (int jp = 0; jp < 4; jp++) {
        float a = x[2 * jp] * inv, b = x[2 * jp + 1] * inv;
        bf16 ha = __float2bfloat16_rn(a), hb = __float2bfloat16_rn(b);
        ((bf162*)sh)[jp] = bf162{ha, hb};
        ((bf162*)sl)[jp] = bf162{__float2bfloat16_rn(a - __bfloat162float(ha)),
                                 __float2bfloat16_rn(b - __bfloat162float(hb))};
    }
}

// -------- ctx[q, h*64+n] = sum_k scores[h,q,k] * V[k, h*64+n] ---------------
// Block 128(q) x 64(n = full head), BK=32 over 2048 keys. V via trans ldmatrix.
#define VST 72   // 64 + 8 pad

__global__ __launch_bounds__(256, 2) void ctx_kernel()
{
    __shared__ bf16 Ssh[128][KST], Ssl[128][KST];
    __shared__ bf16 Vsh[32][VST],  Vsl[32][VST];
    const int tid = threadIdx.x, lane = tid & 31, warp = tid >> 5;
    const int wm = warp & 3, wn = warp >> 2;
    const int h = blockIdx.y;
    const int q0 = blockIdx.x * 128;
    const int ho = h * DH;
    const bf16* Sh = g_Sh + (size_t)h * SEQ * SEQ;
    const bf16* Sl = g_Sl + (size_t)h * SEQ * SEQ;

    const int xr = tid >> 2, xc = (tid & 3) * 8;      // S loader
    const int vr = tid >> 3, vc = (tid & 7) * 8;      // V loader: 32 rows x 8 chunks

    float acc[2][4][4] = {};
    for (int kt = 0; kt < SEQ; kt += 32) {
        *(uint4*)&Ssh[xr][xc]      = *(const uint4*)&Sh[(size_t)(q0 + xr) * SEQ + kt + xc];
        *(uint4*)&Ssh[xr + 64][xc] = *(const uint4*)&Sh[(size_t)(q0 + xr + 64) * SEQ + kt + xc];
        *(uint4*)&Ssl[xr][xc]      = *(const uint4*)&Sl[(size_t)(q0 + xr) * SEQ + kt + xc];
        *(uint4*)&Ssl[xr + 64][xc] = *(const uint4*)&Sl[(size_t)(q0 + xr + 64) * SEQ + kt + xc];
        *(uint4*)&Vsh[vr][vc]      = *(const uint4*)&g_Vh[(size_t)(kt + vr) * ND + ho + vc];
        *(uint4*)&Vsl[vr][vc]      = *(const uint4*)&g_Vl[(size_t)(kt + vr) * ND + ho + vc];
        __syncthreads();
        #pragma unroll
        for (int kk = 0; kk < 32; kk += 16) {
            uint32_t Ah[2][4], Al[2][4], Bh[4][2], Bl[4][2];
            int arow = wm * 32 + (lane & 7) + ((lane >> 3) & 1) * 8;
            int acol = kk + (lane >> 4) * 8;
            ldsm4(Ah[0], smem_u32(&Ssh[arow][acol]));
            ldsm4(Ah[1], smem_u32(&Ssh[arow + 16][acol]));
            ldsm4(Al[0], smem_u32(&Ssl[arow][acol]));
            ldsm4(Al[1], smem_u32(&Ssl[arow + 16][acol]));
            // V is [k][n] k-major -> trans ldmatrix
            int vrow = kk + ((lane >> 3) & 1) * 8 + (lane & 7);
            int vcol = wn * 32 + (lane >> 4) * 8;
            ldsm4t(&Bh[0][0], smem_u32(&Vsh[vrow][vcol]));
            ldsm4t(&Bh[2][0], smem_u32(&Vsh[vrow][vcol + 16]));
            ldsm4t(&Bl[0][0], smem_u32(&Vsl[vrow][vcol]));
            ldsm4t(&Bl[2][0], smem_u32(&Vsl[vrow][vcol + 16]));
            #pragma unroll
            for (int mt = 0; mt < 2; mt++)
                #pragma unroll
                for (int nt = 0; nt < 4; nt++) {
                    mma16816(acc[mt][nt], Ah[mt], Bh[nt]);
                    mma16816(acc[mt][nt], Ah[mt], Bl[nt]);
                    mma16816(acc[mt][nt], Al[mt], Bh[nt]);
                }
        }
        __syncthreads();
    }
    const int r0 = lane >> 2, cc = (lane & 3) * 2;
    #pragma unroll
    for (int mt = 0; mt < 2; mt++)
        #pragma unroll
        for (int nt = 0; nt < 4; nt++) {
            int m = q0 + wm * 32 + mt * 16 + r0;
            int n = ho + wn * 32 + nt * 8 + cc;
            float v0 = acc[mt][nt][0], v1 = acc[mt][nt][1];
            float v2 = acc[mt][nt][2], v3 = acc[mt][nt][3];
            bf16 h0 = __float2bfloat16_rn(v0), h1 = __float2bfloat16_rn(v1);
            bf16 h2 = __float2bfloat16_rn(v2), h3 = __float2bfloat16_rn(v3);
            *(bf162*)&g_ctxh[(size_t)m * ND + n]       = bf162{h0, h1};
            *(bf162*)&g_ctxh[(size_t)(m + 8) * ND + n] = bf162{h2, h3};
            *(bf162*)&g_ctxl[(size_t)m * ND + n] =
                bf162{__float2bfloat16_rn(v0 - __bfloat162float(h0)),
                      __float2bfloat16_rn(v1 - __bfloat162float(h1))};
            *(bf162*)&g_ctxl[(size_t)(m + 8) * ND + n] =
                bf162{__float2bfloat16_rn(v2 - __bfloat162float(h2)),
                      __float2bfloat16_rn(v3 - __bfloat162float(h3))};
        }
}

// ---------------------------------------------------------------------------
extern "C" void kernel_launch(void* const* d_in, const int* in_sizes, int n_in,
                              void* d_out, int out_size)
{
    const float* q      = (const float*)d_in[0];
    const float* k      = (const float*)d_in[1];
    const float* v      = (const float*)d_in[2];
    const float* Wq_w   = (const float*)d_in[3];
    const float* Wq_b   = (const float*)d_in[4];
    const float* Wk_w   = (const float*)d_in[5];
    const float* Wk_b   = (const float*)d_in[6];
    const float* Wv_w   = (const float*)d_in[7];
    const float* Wv_b   = (const float*)d_in[8];
    const float* Wo_w   = (const float*)d_in[9];
    const float* Wo_b   = (const float*)d_in[10];
    const float* pos_emb= (const float*)d_in[11];
    float* out = (float*)d_out;

    bf16 *inqh, *inql, *inkh, *inkl, *invh, *invl;
    bf16 *wqh, *wql, *wkh, *wkl, *wvh, *wvl, *woh, *wol;
    bf16 *Qh, *Ql, *Kh, *Kl, *Vh, *Vl, *ctxh, *ctxl;
    float* Qf;
    cudaGetSymbolAddress((void**)&inqh, g_inqh); cudaGetSymbolAddress((void**)&inql, g_inql);
    cudaGetSymbolAddress((void**)&inkh, g_inkh); cudaGetSymbolAddress((void**)&inkl, g_inkl);
    cudaGetSymbolAddress((void**)&invh, g_invh); cudaGetSymbolAddress((void**)&invl, g_invl);
    cudaGetSymbolAddress((void**)&wqh, g_wqh);   cudaGetSymbolAddress((void**)&wql, g_wql);
    cudaGetSymbolAddress((void**)&wkh, g_wkh);   cudaGetSymbolAddress((void**)&wkl, g_wkl);
    cudaGetSymbolAddress((void**)&wvh, g_wvh);   cudaGetSymbolAddress((void**)&wvl, g_wvl);
    cudaGetSymbolAddress((void**)&woh, g_woh);   cudaGetSymbolAddress((void**)&wol, g_wol);
    cudaGetSymbolAddress((void**)&Qh, g_Qh);     cudaGetSymbolAddress((void**)&Ql, g_Ql);
    cudaGetSymbolAddress((void**)&Kh, g_Kh);     cudaGetSymbolAddress((void**)&Kl, g_Kl);
    cudaGetSymbolAddress((void**)&Vh, g_Vh);     cudaGetSymbolAddress((void**)&Vl, g_Vl);
    cudaGetSymbolAddress((void**)&ctxh, g_ctxh); cudaGetSymbolAddress((void**)&ctxl, g_ctxl);
    cudaGetSymbolAddress((void**)&Qf, g_Q);

    const int nIn = SEQ * ND / 1024;   // split grid for 2M-element arrays
    const int nW  = ND * ND / 1024;

    split_kernel<<<nIn, 256>>>(q, inqh, inql);
    split_kernel<<<nIn, 256>>>(k, inkh, inkl);
    split_kernel<<<nIn, 256>>>(v, invh, invl);
    split_kernel<<<nW, 256>>>(Wq_w, wqh, wql);
    split_kernel<<<nW, 256>>>(Wk_w, wkh, wkl);
    split_kernel<<<nW, 256>>>(Wv_w, wvh, wvl);
    split_kernel<<<nW, 256>>>(Wo_w, woh, wol);

    dim3 gProj(ND / 64, SEQ / 128);   // (16, 16)
    mm_bias_kernel<<<gProj, 256>>>(inqh, inql, wqh, wql, Wq_b, Qf, Qh, Ql);
    mm_bias_kernel<<<gProj, 256>>>(inkh, inkl, wkh, wkl, Wk_b, nullptr, Kh, Kl);
    mm_bias_kernel<<<gProj, 256>>>(invh, invl, wvh, wvl, Wv_b, nullptr, Vh, Vl);

    qk_kernel<<<dim3(SEQ / 64, SEQ / 128, NH), 256>>>();
    li_kernel<<<dim3(SEQ / 64, NH), 256>>>(pos_emb);
    cope_softmax_kernel<<<dim3(SEQ, NH), 256>>>();
    ctx_kernel<<<dim3(SEQ / 128, NH), 256>>>();

    mm_bias_kernel<<<gProj, 256>>>(ctxh, ctxl, woh, wol, Wo_b, out, nullptr, nullptr);
}